// round 14
// baseline (speedup 1.0000x reference)
#include <cuda_runtime.h>
#include <cuda_bf16.h>
#include <cuda_fp16.h>
#include <cstdint>
#include <math.h>

#define Sdim 256
#define Idim 512
#define Cdim 256
#define HD   256
#define SI   (Sdim*Idim)
#define APITCH 132
#define BPITCH 36

// ---------------- device scratch ----------------
__device__ float g_KV[(size_t)SI * 64];     // transposed: [i][t][j]  (i*Sdim+t)*64+j
__device__ float g_Xsum[Idim * Cdim];
__device__ float g_Qbar[Idim * HD];
__device__ float g_Wgt[Idim * HD];
__device__ uint32_t g_Xn[(size_t)SI * 128]; // LN(x) as fp16 pairs, row-major
// chunk-major packed fp16-pair weights (hi only): [(g*4+kc)*8192 + n*32 + kp]
__device__ uint32_t g_B32hi[2 * 4 * 8192];
// Wkv fp16 pairs: [n (0..63)][kp (0..127)]
__device__ uint32_t g_KVW32hi[64 * 128];

__device__ __forceinline__ uint32_t pack_f16(float a, float b) {
    __half2 t = __floats2half2_rn(a, b);
    return *(uint32_t*)&t;
}
__device__ __forceinline__ uint32_t smem_u32(const void* p) {
    uint32_t a;
    asm("{ .reg .u64 t; cvta.to.shared.u64 t, %1; cvt.u32.u64 %0, t; }" : "=r"(a) : "l"(p));
    return a;
}
__device__ __forceinline__ void ldsm_x4(uint32_t& r0, uint32_t& r1, uint32_t& r2, uint32_t& r3,
                                        uint32_t addr) {
    asm volatile("ldmatrix.sync.aligned.m8n8.x4.shared.b16 {%0,%1,%2,%3}, [%4];"
                 : "=r"(r0), "=r"(r1), "=r"(r2), "=r"(r3) : "r"(addr));
}

// ---------------- prep: Wg/Wo fp16 pack + Xsum zero ----------------
__global__ void prep_weights_kernel(const float* __restrict__ Wg, const float* __restrict__ Wo) {
    int d = blockIdx.x * blockDim.x + threadIdx.x;
    if (d >= 65536) return;
    g_Xsum[d] = 0.f;
    g_Xsum[d + 65536] = 0.f;
    int n  = d & 255;
    int kp = (d >> 8) & 31;
    int kc = (d >> 13) & 3;
    int g  = d >> 15;
    const float* W = g ? Wo : Wg;
    int k0 = kc * 64 + kp * 2;
    float w0 = W[k0 * 256 + n], w1 = W[(k0 + 1) * 256 + n];
    int idx = (g * 4 + kc) * 8192 + n * 32 + kp;
    g_B32hi[idx] = pack_f16(w0, w1);
}

// ---------------- prep: Wk|Wv fp16 pack, [n][kp] pair-major ----------------
__global__ void prep_kv_kernel(const float* __restrict__ Wk, const float* __restrict__ Wv) {
    int d = blockIdx.x * blockDim.x + threadIdx.x;
    if (d >= 64 * 128) return;
    int n = d >> 7, kp = d & 127;
    int k0 = kp * 2;
    float w0 = (n < 32) ? Wk[k0 * 32 + n] : Wv[k0 * 32 + (n - 32)];
    float w1 = (n < 32) ? Wk[(k0 + 1) * 32 + n] : Wv[(k0 + 1) * 32 + (n - 32)];
    g_KVW32hi[d] = pack_f16(w0, w1);
}

// ================= pass 1: LN + K/V proj via mma + xn column-sum + g_Xn write =================
#define P1_XNH 512
#define P1_BH  (512 + 64 * 132)
#define P1_SMEM_U32 (P1_BH + 64 * 132)

__global__ __launch_bounds__(256)
void pass1_kernel(const float* __restrict__ x, const float* __restrict__ gamma,
                  const float* __restrict__ beta) {
    extern __shared__ uint32_t smu[];
    float* fsm = (float*)smu;
    const int tid = threadIdx.x;
    const int wid = tid >> 5, lane = tid & 31;
    const int gid = lane >> 2, tig = lane & 3;
    const int mw = wid >> 1, nw = wid & 1;
    const int m0w = mw * 16, n0w = nw * 32;
    const int i0 = blockIdx.x * 64, s0 = blockIdx.y * 8;
    const int r = tid >> 2, q = tid & 3;

    fsm[tid] = gamma[tid];
    fsm[256 + tid] = beta[tid];
    for (int idx = tid; idx < 8192; idx += 256) {
        int n = idx >> 7, kp = idx & 127;
        smu[P1_BH + n * 132 + kp] = g_KVW32hi[idx];
    }

    float xa[64];
#pragma unroll
    for (int j = 0; j < 64; ++j) xa[j] = 0.f;
    __syncthreads();

    for (int ss = 0; ss < 8; ++ss) {
        const int s = s0 + ss;
        const size_t grow = (size_t)(s * Idim + i0 + r);
        const float* xr = x + grow * Cdim;
        uint32_t* xnout = g_Xn + grow * 128;

        float sum = 0.f, sq = 0.f;
#pragma unroll 8
        for (int j = 0; j < 32; ++j) {
            float2 v = *(const float2*)(xr + 8 * j + 2 * q);
            sum += v.x + v.y;
            sq  += v.x * v.x + v.y * v.y;
        }
        sum += __shfl_xor_sync(0xffffffffu, sum, 1);
        sq  += __shfl_xor_sync(0xffffffffu, sq, 1);
        sum += __shfl_xor_sync(0xffffffffu, sum, 2);
        sq  += __shfl_xor_sync(0xffffffffu, sq, 2);
        float mu  = sum * (1.f / 256.f);
        float var = sq * (1.f / 256.f) - mu * mu;
        float rs  = rsqrtf(var + 1e-5f);
#pragma unroll 8
        for (int j = 0; j < 32; ++j) {
            int c = 8 * j + 2 * q;
            float2 v = *(const float2*)(xr + c);
            float xn0 = (v.x - mu) * rs * fsm[c] + fsm[256 + c];
            float xn1 = (v.y - mu) * rs * fsm[c + 1] + fsm[256 + c + 1];
            xa[2 * j]     += xn0;
            xa[2 * j + 1] += xn1;
            uint32_t pk = pack_f16(xn0, xn1);
            smu[P1_XNH + r * 132 + 4 * j + q] = pk;
            xnout[4 * j + q] = pk;
        }
        __syncthreads();

        float acc[4][4];
#pragma unroll
        for (int ni = 0; ni < 4; ++ni)
#pragma unroll
            for (int f = 0; f < 4; ++f) acc[ni][f] = 0.f;

#pragma unroll 4
        for (int ks = 0; ks < 16; ++ks) {
            const uint32_t* Ar = smu + P1_XNH + (m0w + gid) * 132 + ks * 8 + tig;
            uint32_t a0 = Ar[0], a1 = Ar[8 * 132], a2 = Ar[4], a3 = Ar[8 * 132 + 4];
#pragma unroll
            for (int ni = 0; ni < 4; ++ni) {
                const uint32_t* Br = smu + P1_BH + (n0w + ni * 8 + gid) * 132 + ks * 8 + tig;
                uint32_t b0 = Br[0], b1 = Br[4];
                asm volatile(
                    "mma.sync.aligned.m16n8k16.row.col.f32.f16.f16.f32 "
                    "{%0,%1,%2,%3}, {%4,%5,%6,%7}, {%8,%9}, {%0,%1,%2,%3};"
                    : "+f"(acc[ni][0]), "+f"(acc[ni][1]),
                      "+f"(acc[ni][2]), "+f"(acc[ni][3])
                    : "r"(a0), "r"(a1), "r"(a2), "r"(a3), "r"(b0), "r"(b1));
            }
        }

#pragma unroll
        for (int ni = 0; ni < 4; ++ni) {
            int c = n0w + ni * 8 + tig * 2;
            int r0 = m0w + gid;
            float2 v0 = make_float2(acc[ni][0], acc[ni][1]);
            float2 v1 = make_float2(acc[ni][2], acc[ni][3]);
            *(float2*)(g_KV + ((size_t)(i0 + r0) * Sdim + s) * 64 + c) = v0;
            *(float2*)(g_KV + ((size_t)(i0 + r0 + 8) * Sdim + s) * 64 + c) = v1;
        }
        __syncthreads();
    }

#pragma unroll 4
    for (int j = 0; j < 32; ++j) {
        int c = 8 * j + 2 * q;
        atomicAdd(&g_Xsum[(i0 + r) * 256 + c],     xa[2 * j]);
        atomicAdd(&g_Xsum[(i0 + r) * 256 + c + 1], xa[2 * j + 1]);
    }
}

// ================= pass 2q: Qbar = (Xsum/S) @ Wq, grid (64,8) =================
__global__ __launch_bounds__(256)
void pass2q_kernel(const float* __restrict__ Wq) {
    extern __shared__ float sm[];
    float* xbt = sm;            // 8*256
    float* wqs = sm + 2048;     // 256*32

    const int tid = threadIdx.x;
    const int i0 = blockIdx.x * 8, n0 = blockIdx.y * 32;

    for (int idx = tid; idx < 2048; idx += 256)
        xbt[idx] = g_Xsum[i0 * 256 + idx] * (1.f / (float)Sdim);
    for (int idx = tid; idx < 2048; idx += 256) {
        int kk = idx >> 3, c4 = idx & 7;
        ((float4*)(wqs + kk * 32))[c4] = ((const float4*)(Wq + kk * 256 + n0))[c4];
    }
    __syncthreads();

    const int col = tid & 31, rr = tid >> 5;
    float a0 = 0.f;
#pragma unroll 8
    for (int kk = 0; kk < 256; ++kk)
        a0 += xbt[rr * 256 + kk] * wqs[kk * 32 + col];
    g_Qbar[(i0 + rr) * 256 + n0 + col] = a0;
}

// ================= pass 2a: attention per column (coalesced KV) =================
#define KVP 65
__global__ __launch_bounds__(256, 1)
void pass2a_kernel() {
    extern __shared__ float sm[];
    float* qb  = sm;
    float* kvs = sm + 256;
    float* sc  = kvs + 256 * KVP;

    const int i = blockIdx.x, tid = threadIdx.x;
    qb[tid] = g_Qbar[i * 256 + tid];

    const float4* src = (const float4*)(g_KV + (size_t)i * Sdim * 64);
    for (int idx = tid; idx < 256 * 16; idx += 256) {
        int t = idx >> 4, j4 = idx & 15;
        float4 v = src[idx];
        float* d = kvs + t * KVP + j4 * 4;
        d[0] = v.x; d[1] = v.y; d[2] = v.z; d[3] = v.w;
    }
    __syncthreads();

    const int h = tid >> 5, lt = tid & 31;
    float sv[8];
#pragma unroll
    for (int k = 0; k < 8; ++k) {
        int t = lt + 32 * k;
        float s = 0.f;
#pragma unroll
        for (int d = 0; d < 32; ++d) s += qb[h * 32 + d] * kvs[t * KVP + d];
        sv[k] = s * 0.17677669529663687f;
    }
    float mx = sv[0];
#pragma unroll
    for (int k = 1; k < 8; ++k) mx = fmaxf(mx, sv[k]);
#pragma unroll
    for (int off = 16; off > 0; off >>= 1) mx = fmaxf(mx, __shfl_xor_sync(0xffffffffu, mx, off));
    float sum = 0.f;
#pragma unroll
    for (int k = 0; k < 8; ++k) { sv[k] = __expf(sv[k] - mx); sum += sv[k]; }
#pragma unroll
    for (int off = 16; off > 0; off >>= 1) sum += __shfl_xor_sync(0xffffffffu, sum, off);
    float rinv = 1.f / sum;
#pragma unroll
    for (int k = 0; k < 8; ++k) sc[h * 256 + lt + 32 * k] = sv[k] * rinv;
    __syncthreads();

    const int d = tid & 31;
    float wacc = 0.f;
#pragma unroll 4
    for (int t = 0; t < 256; ++t) wacc += sc[h * 256 + t] * kvs[t * KVP + 32 + d];
    g_Wgt[(size_t)i * 256 + h * 32 + d] = wacc;
}

// ================= pass 2b: mma.sync fp16, full-B-resident + ldmatrix =================
// smem (u32): 0: sbg[256], 256: sbo[256], 512: A[128][132], 17408: B[4 chunks][256][36]
#define SM_AH 512
#define SM_B  17408
#define SM2B_U32 (17408 + 4 * 9216)
#define SM2B_BYTES (SM2B_U32 * 4)

__device__ __forceinline__ void stage_b_full(uint32_t* smu, int g, int tid) {
    const uint4* src = (const uint4*)g_B32hi + (size_t)g * 8192;
#pragma unroll
    for (int t = 0; t < 32; ++t) {
        int u = tid + t * 256;                 // uint4 index in [0, 8192)
        int kc = u >> 11, rem = u & 2047;
        int n = rem >> 3, kq = rem & 7;
        *((uint4*)(smu + SM_B + kc * 9216 + n * 36) + kq) = src[u];
    }
}

__device__ __forceinline__ void mma_gemm(const uint32_t smbase, const uint32_t* a_base,
                                         const uint32_t* b_base, int gid, int tig,
                                         float acc[4][8][4]) {
#pragma unroll
    for (int kc = 0; kc < 4; ++kc) {
#pragma unroll
        for (int s = 0; s < 4; ++s) {
            const uint32_t akoff = (uint32_t)(kc * 32 + s * 8) * 4;
            const uint32_t bkoff = (uint32_t)(kc * 9216 + s * 8) * 4;
            uint32_t a[4][4], bb[4][4];
#pragma unroll
            for (int mi = 0; mi < 4; ++mi)
                ldsm_x4(a[mi][0], a[mi][1], a[mi][2], a[mi][3], a_base[mi] + akoff);
#pragma unroll
            for (int np = 0; np < 4; ++np)
                ldsm_x4(bb[np][0], bb[np][1], bb[np][2], bb[np][3], b_base[np] + bkoff);
#pragma unroll
            for (int ni = 0; ni < 8; ++ni) {
                uint32_t b0 = bb[ni >> 1][(ni & 1) * 2];
                uint32_t b1 = bb[ni >> 1][(ni & 1) * 2 + 1];
#pragma unroll
                for (int mi = 0; mi < 4; ++mi) {
                    asm volatile(
                        "mma.sync.aligned.m16n8k16.row.col.f32.f16.f16.f32 "
                        "{%0,%1,%2,%3}, {%4,%5,%6,%7}, {%8,%9}, {%0,%1,%2,%3};"
                        : "+f"(acc[mi][ni][0]), "+f"(acc[mi][ni][1]),
                          "+f"(acc[mi][ni][2]), "+f"(acc[mi][ni][3])
                        : "r"(a[mi][0]), "r"(a[mi][1]), "r"(a[mi][2]), "r"(a[mi][3]),
                          "r"(b0), "r"(b1));
                }
            }
        }
    }
}

__global__ __launch_bounds__(256, 1)
void pass2b_mma_kernel(const float* __restrict__ bg, const float* __restrict__ bo,
                       float* __restrict__ out) {
    extern __shared__ uint32_t smu[];
    float* fsm = (float*)smu;
    const uint32_t smbase = smem_u32(smu);
    const int tid = threadIdx.x;
    const int wid = tid >> 5, lane = tid & 31;
    const int gid = lane >> 2, tig = lane & 3;
    const int m0 = (wid >> 2) * 64, n0 = (wid & 3) * 64;
    const size_t r0 = (size_t)blockIdx.x * 128;
    const int i0 = (int)(r0 % Idim);

    fsm[tid] = bg[tid];
    fsm[256 + tid] = bo[tid];

    // ldmatrix lane base addresses (bytes)
    uint32_t a_base[4], b_base[4];
    {
        int arow = (lane & 7) + 8 * ((lane >> 3) & 1);
        int akl  = 4 * (lane >> 4);
#pragma unroll
        for (int mi = 0; mi < 4; ++mi)
            a_base[mi] = smbase + (uint32_t)(SM_AH + (m0 + mi * 16 + arow) * APITCH + akl) * 4;
        int brow = (lane & 7) + 8 * ((lane >> 4) & 1);
        int bkl  = 4 * ((lane >> 3) & 1);
#pragma unroll
        for (int np = 0; np < 4; ++np)
            b_base[np] = smbase + (uint32_t)(SM_B + (n0 + np * 16 + brow) * BPITCH + bkl) * 4;
    }

    // ---- stage A (pre-LN'd fp16 xn tile) + full Wg ----
    {
        const uint4* xn = (const uint4*)(g_Xn + r0 * 128);
#pragma unroll
        for (int t = 0; t < 16; ++t) {
            int idx4 = tid + t * 256;
            int row = idx4 >> 5, c4 = idx4 & 31;
            *(uint4*)(smu + SM_AH + row * APITCH + c4 * 4) = xn[idx4];
        }
    }
    stage_b_full(smu, 0, tid);
    __syncthreads();

    float acc[4][8][4] = {};

    // ---- GEMM1: xn @ Wg (no intra-GEMM syncs) ----
    mma_gemm(smbase, a_base, b_base, gid, tig, acc);
    __syncthreads();   // all warps done reading A and B

    // ---- stage Wo (issue loads first), then epilogue 1 ----
    stage_b_full(smu, 1, tid);
#pragma unroll
    for (int mi = 0; mi < 4; ++mi) {
#pragma unroll
        for (int ni = 0; ni < 8; ++ni) {
            int c = n0 + ni * 8 + tig * 2;
#pragma unroll
            for (int half = 0; half < 2; ++half) {
                int r = m0 + mi * 16 + gid + half * 8;
                float2 w = *(const float2*)(g_Wgt + (size_t)(i0 + r) * 256 + c);
                float t0 = acc[mi][ni][half * 2 + 0] + fsm[c];
                float t1 = acc[mi][ni][half * 2 + 1] + fsm[c + 1];
                float v0 = w.x / (1.f + __expf(-t0));
                float v1 = w.y / (1.f + __expf(-t1));
                smu[SM_AH + r * APITCH + (c >> 1)] = pack_f16(v0, v1);
                acc[mi][ni][half * 2 + 0] = 0.f;
                acc[mi][ni][half * 2 + 1] = 0.f;
            }
        }
    }
    __syncthreads();

    // ---- GEMM2: val @ Wo ----
    mma_gemm(smbase, a_base, b_base, gid, tig, acc);

    // ---- epilogue 2: out = acc + bo ----
#pragma unroll
    for (int mi = 0; mi < 4; ++mi) {
#pragma unroll
        for (int ni = 0; ni < 8; ++ni) {
            int c = n0 + ni * 8 + tig * 2;
#pragma unroll
            for (int half = 0; half < 2; ++half) {
                int r = m0 + mi * 16 + gid + half * 8;
                float2 v;
                v.x = acc[mi][ni][half * 2 + 0] + fsm[256 + c];
                v.y = acc[mi][ni][half * 2 + 1] + fsm[256 + c + 1];
                *(float2*)(out + (r0 + r) * Cdim + c) = v;
            }
        }
    }
}

// ---------------- launch ----------------
extern "C" void kernel_launch(void* const* d_in, const int* in_sizes, int n_in,
                              void* d_out, int out_size) {
    const float* x     = (const float*)d_in[0];
    const float* gamma = (const float*)d_in[1];
    const float* beta  = (const float*)d_in[2];
    const float* Wq    = (const float*)d_in[3];
    const float* Wk    = (const float*)d_in[4];
    const float* Wv    = (const float*)d_in[5];
    const float* Wg    = (const float*)d_in[6];
    const float* bg    = (const float*)d_in[7];
    const float* Wo    = (const float*)d_in[8];
    const float* bo    = (const float*)d_in[9];
    float* out = (float*)d_out;

    const int SMEM1  = P1_SMEM_U32 * 4;
    const int SMEM2Q = (2048 + 256 * 32) * 4;
    const int SMEM2A = (256 + 256 * KVP + 8 * 256) * 4;

    cudaFuncSetAttribute(pass1_kernel,      cudaFuncAttributeMaxDynamicSharedMemorySize, SMEM1);
    cudaFuncSetAttribute(pass2q_kernel,     cudaFuncAttributeMaxDynamicSharedMemorySize, SMEM2Q);
    cudaFuncSetAttribute(pass2a_kernel,     cudaFuncAttributeMaxDynamicSharedMemorySize, SMEM2A);
    cudaFuncSetAttribute(pass2b_mma_kernel, cudaFuncAttributeMaxDynamicSharedMemorySize, SM2B_BYTES);

    prep_weights_kernel<<<256, 256>>>(Wg, Wo);
    prep_kv_kernel<<<32, 256>>>(Wk, Wv);
    pass1_kernel<<<dim3(Idim / 64, Sdim / 8), 256, SMEM1>>>(x, gamma, beta);
    pass2q_kernel<<<dim3(64, 8), 256, SMEM2Q>>>(Wq);
    pass2a_kernel<<<Idim, 256, SMEM2A>>>();
    pass2b_mma_kernel<<<SI / 128, 256, SM2B_BYTES>>>(bg, bo, out);
}

// round 15
// speedup vs baseline: 1.0362x; 1.0362x over previous
#include <cuda_runtime.h>
#include <cuda_bf16.h>
#include <cuda_fp16.h>
#include <cstdint>
#include <math.h>

#define Sdim 256
#define Idim 512
#define Cdim 256
#define HD   256
#define SI   (Sdim*Idim)
#define APITCH 132
#define BPITCH 36

// ---------------- device scratch ----------------
__device__ float g_KV[(size_t)SI * 64];     // transposed: [i][t][j]  (i*Sdim+t)*64+j
__device__ float g_Xsum[Idim * Cdim];
__device__ float g_Wgt[Idim * HD];
__device__ uint32_t g_Xn[(size_t)SI * 128]; // LN(x) as fp16 pairs, row-major
// chunk-major packed fp16-pair weights (hi only): [(g*4+kc)*8192 + n*32 + kp]
__device__ uint32_t g_B32hi[2 * 4 * 8192];
// Wkv fp16 pairs: [n (0..63)][kp (0..127)]
__device__ uint32_t g_KVW32hi[64 * 128];

__device__ __forceinline__ uint32_t pack_f16(float a, float b) {
    __half2 t = __floats2half2_rn(a, b);
    return *(uint32_t*)&t;
}
__device__ __forceinline__ uint32_t smem_u32(const void* p) {
    uint32_t a;
    asm("{ .reg .u64 t; cvta.to.shared.u64 t, %1; cvt.u32.u64 %0, t; }" : "=r"(a) : "l"(p));
    return a;
}
__device__ __forceinline__ void ldsm_x4(uint32_t& r0, uint32_t& r1, uint32_t& r2, uint32_t& r3,
                                        uint32_t addr) {
    asm volatile("ldmatrix.sync.aligned.m8n8.x4.shared.b16 {%0,%1,%2,%3}, [%4];"
                 : "=r"(r0), "=r"(r1), "=r"(r2), "=r"(r3) : "r"(addr));
}

// ---------------- prep: Xsum zero + Wg/Wo pack + Wkv pack ----------------
__global__ void prep_kernel(const float* __restrict__ Wg, const float* __restrict__ Wo,
                            const float* __restrict__ Wk, const float* __restrict__ Wv) {
    int d = blockIdx.x * blockDim.x + threadIdx.x;   // grid 512*256 = 131072
    g_Xsum[d] = 0.f;
    if (d < 65536) {
        int n  = d & 255;
        int kp = (d >> 8) & 31;
        int kc = (d >> 13) & 3;
        int g  = d >> 15;
        const float* W = g ? Wo : Wg;
        int k0 = kc * 64 + kp * 2;
        float w0 = W[k0 * 256 + n], w1 = W[(k0 + 1) * 256 + n];
        g_B32hi[(g * 4 + kc) * 8192 + n * 32 + kp] = pack_f16(w0, w1);
    }
    if (d < 8192) {
        int n = d >> 7, kp = d & 127;
        int k0 = kp * 2;
        float w0 = (n < 32) ? Wk[k0 * 32 + n] : Wv[k0 * 32 + (n - 32)];
        float w1 = (n < 32) ? Wk[(k0 + 1) * 32 + n] : Wv[(k0 + 1) * 32 + (n - 32)];
        g_KVW32hi[d] = pack_f16(w0, w1);
    }
}

// ================= pass 1: LN + K/V proj via mma + xn column-sum + g_Xn write =================
#define P1_XNH 512
#define P1_BH  (512 + 64 * 132)
#define P1_SMEM_U32 (P1_BH + 64 * 132)

__global__ __launch_bounds__(256)
void pass1_kernel(const float* __restrict__ x, const float* __restrict__ gamma,
                  const float* __restrict__ beta) {
    extern __shared__ uint32_t smu[];
    float* fsm = (float*)smu;
    const int tid = threadIdx.x;
    const int wid = tid >> 5, lane = tid & 31;
    const int gid = lane >> 2, tig = lane & 3;
    const int mw = wid >> 1, nw = wid & 1;
    const int m0w = mw * 16, n0w = nw * 32;
    const int i0 = blockIdx.x * 64, s0 = blockIdx.y * 8;
    const int r = tid >> 2, q = tid & 3;

    fsm[tid] = gamma[tid];
    fsm[256 + tid] = beta[tid];
    for (int idx = tid; idx < 8192; idx += 256) {
        int n = idx >> 7, kp = idx & 127;
        smu[P1_BH + n * 132 + kp] = g_KVW32hi[idx];
    }

    float xa[64];
#pragma unroll
    for (int j = 0; j < 64; ++j) xa[j] = 0.f;
    __syncthreads();

    for (int ss = 0; ss < 8; ++ss) {
        const int s = s0 + ss;
        const size_t grow = (size_t)(s * Idim + i0 + r);
        const float* xr = x + grow * Cdim;
        uint32_t* xnout = g_Xn + grow * 128;

        float sum = 0.f, sq = 0.f;
#pragma unroll 8
        for (int j = 0; j < 32; ++j) {
            float2 v = *(const float2*)(xr + 8 * j + 2 * q);
            sum += v.x + v.y;
            sq  += v.x * v.x + v.y * v.y;
        }
        sum += __shfl_xor_sync(0xffffffffu, sum, 1);
        sq  += __shfl_xor_sync(0xffffffffu, sq, 1);
        sum += __shfl_xor_sync(0xffffffffu, sum, 2);
        sq  += __shfl_xor_sync(0xffffffffu, sq, 2);
        float mu  = sum * (1.f / 256.f);
        float var = sq * (1.f / 256.f) - mu * mu;
        float rs  = rsqrtf(var + 1e-5f);
#pragma unroll 8
        for (int j = 0; j < 32; ++j) {
            int c = 8 * j + 2 * q;
            float2 v = *(const float2*)(xr + c);
            float xn0 = (v.x - mu) * rs * fsm[c] + fsm[256 + c];
            float xn1 = (v.y - mu) * rs * fsm[c + 1] + fsm[256 + c + 1];
            xa[2 * j]     += xn0;
            xa[2 * j + 1] += xn1;
            uint32_t pk = pack_f16(xn0, xn1);
            smu[P1_XNH + r * 132 + 4 * j + q] = pk;
            xnout[4 * j + q] = pk;
        }
        __syncthreads();

        float acc[4][4];
#pragma unroll
        for (int ni = 0; ni < 4; ++ni)
#pragma unroll
            for (int f = 0; f < 4; ++f) acc[ni][f] = 0.f;

#pragma unroll 4
        for (int ks = 0; ks < 16; ++ks) {
            const uint32_t* Ar = smu + P1_XNH + (m0w + gid) * 132 + ks * 8 + tig;
            uint32_t a0 = Ar[0], a1 = Ar[8 * 132], a2 = Ar[4], a3 = Ar[8 * 132 + 4];
#pragma unroll
            for (int ni = 0; ni < 4; ++ni) {
                const uint32_t* Br = smu + P1_BH + (n0w + ni * 8 + gid) * 132 + ks * 8 + tig;
                uint32_t b0 = Br[0], b1 = Br[4];
                asm volatile(
                    "mma.sync.aligned.m16n8k16.row.col.f32.f16.f16.f32 "
                    "{%0,%1,%2,%3}, {%4,%5,%6,%7}, {%8,%9}, {%0,%1,%2,%3};"
                    : "+f"(acc[ni][0]), "+f"(acc[ni][1]),
                      "+f"(acc[ni][2]), "+f"(acc[ni][3])
                    : "r"(a0), "r"(a1), "r"(a2), "r"(a3), "r"(b0), "r"(b1));
            }
        }

#pragma unroll
        for (int ni = 0; ni < 4; ++ni) {
            int c = n0w + ni * 8 + tig * 2;
            int r0 = m0w + gid;
            float2 v0 = make_float2(acc[ni][0], acc[ni][1]);
            float2 v1 = make_float2(acc[ni][2], acc[ni][3]);
            *(float2*)(g_KV + ((size_t)(i0 + r0) * Sdim + s) * 64 + c) = v0;
            *(float2*)(g_KV + ((size_t)(i0 + r0 + 8) * Sdim + s) * 64 + c) = v1;
        }
        __syncthreads();
    }

#pragma unroll 4
    for (int j = 0; j < 32; ++j) {
        int c = 8 * j + 2 * q;
        atomicAdd(&g_Xsum[(i0 + r) * 256 + c],     xa[2 * j]);
        atomicAdd(&g_Xsum[(i0 + r) * 256 + c + 1], xa[2 * j + 1]);
    }
}

// ================= pass 2a: inline Qbar + attention per column =================
#define KVP 65
__global__ __launch_bounds__(256, 1)
void pass2a_kernel(const float* __restrict__ Wq) {
    extern __shared__ float sm[];
    float* xb  = sm;                 // 256
    float* qb  = sm + 256;           // 256
    float* kvs = sm + 512;           // 256*KVP
    float* sc  = kvs + 256 * KVP;    // 8*256

    const int i = blockIdx.x, tid = threadIdx.x;
    xb[tid] = g_Xsum[i * 256 + tid] * (1.f / (float)Sdim);

    // stage KV tile into registers (contiguous 64KB block per column i)
    float4 kvr[16];
    {
        const float4* src = (const float4*)(g_KV + (size_t)i * Sdim * 64);
#pragma unroll
        for (int t = 0; t < 16; ++t) kvr[t] = src[tid + t * 256];
    }
    __syncthreads();   // xb ready

    // Qbar row for this column: q = sum_c xb[c] * Wq[c*256 + tid]  (coalesced, L2-cached)
    {
        float q0 = 0.f, q1 = 0.f, q2 = 0.f, q3 = 0.f;
#pragma unroll 4
        for (int c = 0; c < 256; c += 4) {
            q0 += xb[c + 0] * Wq[(c + 0) * 256 + tid];
            q1 += xb[c + 1] * Wq[(c + 1) * 256 + tid];
            q2 += xb[c + 2] * Wq[(c + 2) * 256 + tid];
            q3 += xb[c + 3] * Wq[(c + 3) * 256 + tid];
        }
        qb[tid] = (q0 + q1) + (q2 + q3);
    }

    // write staged KV into padded smem
#pragma unroll
    for (int t = 0; t < 16; ++t) {
        int idx = tid + t * 256;
        int tt = idx >> 4, j4 = idx & 15;
        float* d = kvs + tt * KVP + j4 * 4;
        d[0] = kvr[t].x; d[1] = kvr[t].y; d[2] = kvr[t].z; d[3] = kvr[t].w;
    }
    __syncthreads();

    const int h = tid >> 5, lt = tid & 31;
    float sv[8];
#pragma unroll
    for (int k = 0; k < 8; ++k) {
        int t = lt + 32 * k;
        float s = 0.f;
#pragma unroll
        for (int d = 0; d < 32; ++d) s += qb[h * 32 + d] * kvs[t * KVP + d];
        sv[k] = s * 0.17677669529663687f;
    }
    float mx = sv[0];
#pragma unroll
    for (int k = 1; k < 8; ++k) mx = fmaxf(mx, sv[k]);
#pragma unroll
    for (int off = 16; off > 0; off >>= 1) mx = fmaxf(mx, __shfl_xor_sync(0xffffffffu, mx, off));
    float sum = 0.f;
#pragma unroll
    for (int k = 0; k < 8; ++k) { sv[k] = __expf(sv[k] - mx); sum += sv[k]; }
#pragma unroll
    for (int off = 16; off > 0; off >>= 1) sum += __shfl_xor_sync(0xffffffffu, sum, off);
    float rinv = 1.f / sum;
#pragma unroll
    for (int k = 0; k < 8; ++k) sc[h * 256 + lt + 32 * k] = sv[k] * rinv;
    __syncthreads();

    const int d = tid & 31;
    float wacc = 0.f;
#pragma unroll 4
    for (int t = 0; t < 256; ++t) wacc += sc[h * 256 + t] * kvs[t * KVP + 32 + d];
    g_Wgt[(size_t)i * 256 + h * 32 + d] = wacc;
}

// ================= pass 2b: mma.sync fp16, full-B-resident + ldmatrix =================
#define SM_AH 512
#define SM_B  17408
#define SM2B_U32 (17408 + 4 * 9216)
#define SM2B_BYTES (SM2B_U32 * 4)

__device__ __forceinline__ void stage_b_full(uint32_t* smu, int g, int tid) {
    const uint4* src = (const uint4*)g_B32hi + (size_t)g * 8192;
#pragma unroll
    for (int t = 0; t < 32; ++t) {
        int u = tid + t * 256;
        int kc = u >> 11, rem = u & 2047;
        int n = rem >> 3, kq = rem & 7;
        *((uint4*)(smu + SM_B + kc * 9216 + n * 36) + kq) = src[u];
    }
}

__device__ __forceinline__ void mma_gemm(const uint32_t smbase, const uint32_t* a_base,
                                         const uint32_t* b_base, int gid, int tig,
                                         float acc[4][8][4]) {
#pragma unroll
    for (int kc = 0; kc < 4; ++kc) {
#pragma unroll
        for (int s = 0; s < 4; ++s) {
            const uint32_t akoff = (uint32_t)(kc * 32 + s * 8) * 4;
            const uint32_t bkoff = (uint32_t)(kc * 9216 + s * 8) * 4;
            uint32_t a[4][4], bb[4][4];
#pragma unroll
            for (int mi = 0; mi < 4; ++mi)
                ldsm_x4(a[mi][0], a[mi][1], a[mi][2], a[mi][3], a_base[mi] + akoff);
#pragma unroll
            for (int np = 0; np < 4; ++np)
                ldsm_x4(bb[np][0], bb[np][1], bb[np][2], bb[np][3], b_base[np] + bkoff);
#pragma unroll
            for (int ni = 0; ni < 8; ++ni) {
                uint32_t b0 = bb[ni >> 1][(ni & 1) * 2];
                uint32_t b1 = bb[ni >> 1][(ni & 1) * 2 + 1];
#pragma unroll
                for (int mi = 0; mi < 4; ++mi) {
                    asm volatile(
                        "mma.sync.aligned.m16n8k16.row.col.f32.f16.f16.f32 "
                        "{%0,%1,%2,%3}, {%4,%5,%6,%7}, {%8,%9}, {%0,%1,%2,%3};"
                        : "+f"(acc[mi][ni][0]), "+f"(acc[mi][ni][1]),
                          "+f"(acc[mi][ni][2]), "+f"(acc[mi][ni][3])
                        : "r"(a[mi][0]), "r"(a[mi][1]), "r"(a[mi][2]), "r"(a[mi][3]),
                          "r"(b0), "r"(b1));
                }
            }
        }
    }
}

__global__ __launch_bounds__(256, 1)
void pass2b_mma_kernel(const float* __restrict__ bg, const float* __restrict__ bo,
                       float* __restrict__ out) {
    extern __shared__ uint32_t smu[];
    float* fsm = (float*)smu;
    const uint32_t smbase = smem_u32(smu);
    const int tid = threadIdx.x;
    const int wid = tid >> 5, lane = tid & 31;
    const int gid = lane >> 2, tig = lane & 3;
    const int m0 = (wid >> 2) * 64, n0 = (wid & 3) * 64;
    const size_t r0 = (size_t)blockIdx.x * 128;
    const int i0 = (int)(r0 % Idim);

    fsm[tid] = bg[tid];
    fsm[256 + tid] = bo[tid];

    uint32_t a_base[4], b_base[4];
    {
        int arow = (lane & 7) + 8 * ((lane >> 3) & 1);
        int akl  = 4 * (lane >> 4);
#pragma unroll
        for (int mi = 0; mi < 4; ++mi)
            a_base[mi] = smbase + (uint32_t)(SM_AH + (m0 + mi * 16 + arow) * APITCH + akl) * 4;
        int brow = (lane & 7) + 8 * ((lane >> 4) & 1);
        int bkl  = 4 * ((lane >> 3) & 1);
#pragma unroll
        for (int np = 0; np < 4; ++np)
            b_base[np] = smbase + (uint32_t)(SM_B + (n0 + np * 16 + brow) * BPITCH + bkl) * 4;
    }

    {
        const uint4* xn = (const uint4*)(g_Xn + r0 * 128);
#pragma unroll
        for (int t = 0; t < 16; ++t) {
            int idx4 = tid + t * 256;
            int row = idx4 >> 5, c4 = idx4 & 31;
            *(uint4*)(smu + SM_AH + row * APITCH + c4 * 4) = xn[idx4];
        }
    }
    stage_b_full(smu, 0, tid);
    __syncthreads();

    float acc[4][8][4] = {};

    mma_gemm(smbase, a_base, b_base, gid, tig, acc);
    __syncthreads();

    stage_b_full(smu, 1, tid);
#pragma unroll
    for (int mi = 0; mi < 4; ++mi) {
#pragma unroll
        for (int ni = 0; ni < 8; ++ni) {
            int c = n0 + ni * 8 + tig * 2;
#pragma unroll
            for (int half = 0; half < 2; ++half) {
                int r = m0 + mi * 16 + gid + half * 8;
                float2 w = *(const float2*)(g_Wgt + (size_t)(i0 + r) * 256 + c);
                float t0 = acc[mi][ni][half * 2 + 0] + fsm[c];
                float t1 = acc[mi][ni][half * 2 + 1] + fsm[c + 1];
                float v0 = w.x / (1.f + __expf(-t0));
                float v1 = w.y / (1.f + __expf(-t1));
                smu[SM_AH + r * APITCH + (c >> 1)] = pack_f16(v0, v1);
                acc[mi][ni][half * 2 + 0] = 0.f;
                acc[mi][ni][half * 2 + 1] = 0.f;
            }
        }
    }
    __syncthreads();

    mma_gemm(smbase, a_base, b_base, gid, tig, acc);

#pragma unroll
    for (int mi = 0; mi < 4; ++mi) {
#pragma unroll
        for (int ni = 0; ni < 8; ++ni) {
            int c = n0 + ni * 8 + tig * 2;
#pragma unroll
            for (int half = 0; half < 2; ++half) {
                int r = m0 + mi * 16 + gid + half * 8;
                float2 v;
                v.x = acc[mi][ni][half * 2 + 0] + fsm[256 + c];
                v.y = acc[mi][ni][half * 2 + 1] + fsm[256 + c + 1];
                *(float2*)(out + (r0 + r) * Cdim + c) = v;
            }
        }
    }
}

// ---------------- launch ----------------
extern "C" void kernel_launch(void* const* d_in, const int* in_sizes, int n_in,
                              void* d_out, int out_size) {
    const float* x     = (const float*)d_in[0];
    const float* gamma = (const float*)d_in[1];
    const float* beta  = (const float*)d_in[2];
    const float* Wq    = (const float*)d_in[3];
    const float* Wk    = (const float*)d_in[4];
    const float* Wv    = (const float*)d_in[5];
    const float* Wg    = (const float*)d_in[6];
    const float* bg    = (const float*)d_in[7];
    const float* Wo    = (const float*)d_in[8];
    const float* bo    = (const float*)d_in[9];
    float* out = (float*)d_out;

    const int SMEM1  = P1_SMEM_U32 * 4;
    const int SMEM2A = (512 + 256 * KVP + 8 * 256) * 4;

    cudaFuncSetAttribute(pass1_kernel,      cudaFuncAttributeMaxDynamicSharedMemorySize, SMEM1);
    cudaFuncSetAttribute(pass2a_kernel,     cudaFuncAttributeMaxDynamicSharedMemorySize, SMEM2A);
    cudaFuncSetAttribute(pass2b_mma_kernel, cudaFuncAttributeMaxDynamicSharedMemorySize, SM2B_BYTES);

    prep_kernel<<<512, 256>>>(Wg, Wo, Wk, Wv);
    pass1_kernel<<<dim3(Idim / 64, Sdim / 8), 256, SMEM1>>>(x, gamma, beta);
    pass2a_kernel<<<Idim, 256, SMEM2A>>>(Wq);
    pass2b_mma_kernel<<<SI / 128, 256, SM2B_BYTES>>>(bg, bo, out);
}

// round 16
// speedup vs baseline: 1.1733x; 1.1323x over previous
#include <cuda_runtime.h>
#include <cuda_bf16.h>
#include <cuda_fp16.h>
#include <cstdint>
#include <math.h>

#define Sdim 256
#define Idim 512
#define Cdim 256
#define HD   256
#define SI   (Sdim*Idim)
#define APITCH 132
#define BPITCH 36

// ---------------- device scratch ----------------
__device__ float g_KV[(size_t)SI * 64];     // transposed: [i][t][j]  (i*Sdim+t)*64+j
__device__ float g_Xsum[Idim * Cdim];
__device__ float g_Wgt[Idim * HD];
__device__ uint32_t g_Xn[(size_t)SI * 128]; // LN(x) as fp16 pairs, row-major
// chunk-major packed fp16-pair weights (hi only): [(g*4+kc)*8192 + n*32 + kp]
__device__ uint32_t g_B32hi[2 * 4 * 8192];
// Wkv fp16 pairs: [n (0..63)][kp (0..127)]
__device__ uint32_t g_KVW32hi[64 * 128];

__device__ __forceinline__ uint32_t pack_f16(float a, float b) {
    __half2 t = __floats2half2_rn(a, b);
    return *(uint32_t*)&t;
}
__device__ __forceinline__ uint32_t smem_u32(const void* p) {
    uint32_t a;
    asm("{ .reg .u64 t; cvta.to.shared.u64 t, %1; cvt.u32.u64 %0, t; }" : "=r"(a) : "l"(p));
    return a;
}
__device__ __forceinline__ void ldsm_x4(uint32_t& r0, uint32_t& r1, uint32_t& r2, uint32_t& r3,
                                        uint32_t addr) {
    asm volatile("ldmatrix.sync.aligned.m8n8.x4.shared.b16 {%0,%1,%2,%3}, [%4];"
                 : "=r"(r0), "=r"(r1), "=r"(r2), "=r"(r3) : "r"(addr));
}

// ---------------- prep: Xsum zero + Wg/Wo pack + Wkv pack ----------------
__global__ void prep_kernel(const float* __restrict__ Wg, const float* __restrict__ Wo,
                            const float* __restrict__ Wk, const float* __restrict__ Wv) {
    int d = blockIdx.x * blockDim.x + threadIdx.x;   // grid 512*256 = 131072
    g_Xsum[d] = 0.f;
    if (d < 65536) {
        int n  = d & 255;
        int kp = (d >> 8) & 31;
        int kc = (d >> 13) & 3;
        int g  = d >> 15;
        const float* W = g ? Wo : Wg;
        int k0 = kc * 64 + kp * 2;
        float w0 = W[k0 * 256 + n], w1 = W[(k0 + 1) * 256 + n];
        g_B32hi[(g * 4 + kc) * 8192 + n * 32 + kp] = pack_f16(w0, w1);
    }
    if (d < 8192) {
        int n = d >> 7, kp = d & 127;
        int k0 = kp * 2;
        float w0 = (n < 32) ? Wk[k0 * 32 + n] : Wv[k0 * 32 + (n - 32)];
        float w1 = (n < 32) ? Wk[(k0 + 1) * 32 + n] : Wv[(k0 + 1) * 32 + (n - 32)];
        g_KVW32hi[d] = pack_f16(w0, w1);
    }
}

// ================= pass 1: LN + K/V proj via mma + xn column-sum + g_Xn write =================
#define P1_XNH 512
#define P1_BH  (512 + 64 * 132)
#define P1_SMEM_U32 (P1_BH + 64 * 132)

__global__ __launch_bounds__(256)
void pass1_kernel(const float* __restrict__ x, const float* __restrict__ gamma,
                  const float* __restrict__ beta) {
    extern __shared__ uint32_t smu[];
    float* fsm = (float*)smu;
    const int tid = threadIdx.x;
    const int wid = tid >> 5, lane = tid & 31;
    const int gid = lane >> 2, tig = lane & 3;
    const int mw = wid >> 1, nw = wid & 1;
    const int m0w = mw * 16, n0w = nw * 32;
    const int i0 = blockIdx.x * 64, s0 = blockIdx.y * 8;
    const int r = tid >> 2, q = tid & 3;

    fsm[tid] = gamma[tid];
    fsm[256 + tid] = beta[tid];
    for (int idx = tid; idx < 8192; idx += 256) {
        int n = idx >> 7, kp = idx & 127;
        smu[P1_BH + n * 132 + kp] = g_KVW32hi[idx];
    }

    float xa[64];
#pragma unroll
    for (int j = 0; j < 64; ++j) xa[j] = 0.f;
    __syncthreads();

    for (int ss = 0; ss < 8; ++ss) {
        const int s = s0 + ss;
        const size_t grow = (size_t)(s * Idim + i0 + r);
        const float* xr = x + grow * Cdim;
        uint32_t* xnout = g_Xn + grow * 128;

        float sum = 0.f, sq = 0.f;
#pragma unroll 8
        for (int j = 0; j < 32; ++j) {
            float2 v = *(const float2*)(xr + 8 * j + 2 * q);
            sum += v.x + v.y;
            sq  += v.x * v.x + v.y * v.y;
        }
        sum += __shfl_xor_sync(0xffffffffu, sum, 1);
        sq  += __shfl_xor_sync(0xffffffffu, sq, 1);
        sum += __shfl_xor_sync(0xffffffffu, sum, 2);
        sq  += __shfl_xor_sync(0xffffffffu, sq, 2);
        float mu  = sum * (1.f / 256.f);
        float var = sq * (1.f / 256.f) - mu * mu;
        float rs  = rsqrtf(var + 1e-5f);
#pragma unroll 8
        for (int j = 0; j < 32; ++j) {
            int c = 8 * j + 2 * q;
            float2 v = *(const float2*)(xr + c);
            float xn0 = (v.x - mu) * rs * fsm[c] + fsm[256 + c];
            float xn1 = (v.y - mu) * rs * fsm[c + 1] + fsm[256 + c + 1];
            xa[2 * j]     += xn0;
            xa[2 * j + 1] += xn1;
            uint32_t pk = pack_f16(xn0, xn1);
            smu[P1_XNH + r * 132 + 4 * j + q] = pk;
            xnout[4 * j + q] = pk;
        }
        __syncthreads();

        float acc[4][4];
#pragma unroll
        for (int ni = 0; ni < 4; ++ni)
#pragma unroll
            for (int f = 0; f < 4; ++f) acc[ni][f] = 0.f;

#pragma unroll 4
        for (int ks = 0; ks < 16; ++ks) {
            const uint32_t* Ar = smu + P1_XNH + (m0w + gid) * 132 + ks * 8 + tig;
            uint32_t a0 = Ar[0], a1 = Ar[8 * 132], a2 = Ar[4], a3 = Ar[8 * 132 + 4];
#pragma unroll
            for (int ni = 0; ni < 4; ++ni) {
                const uint32_t* Br = smu + P1_BH + (n0w + ni * 8 + gid) * 132 + ks * 8 + tig;
                uint32_t b0 = Br[0], b1 = Br[4];
                asm volatile(
                    "mma.sync.aligned.m16n8k16.row.col.f32.f16.f16.f32 "
                    "{%0,%1,%2,%3}, {%4,%5,%6,%7}, {%8,%9}, {%0,%1,%2,%3};"
                    : "+f"(acc[ni][0]), "+f"(acc[ni][1]),
                      "+f"(acc[ni][2]), "+f"(acc[ni][3])
                    : "r"(a0), "r"(a1), "r"(a2), "r"(a3), "r"(b0), "r"(b1));
            }
        }

#pragma unroll
        for (int ni = 0; ni < 4; ++ni) {
            int c = n0w + ni * 8 + tig * 2;
            int r0 = m0w + gid;
            float2 v0 = make_float2(acc[ni][0], acc[ni][1]);
            float2 v1 = make_float2(acc[ni][2], acc[ni][3]);
            *(float2*)(g_KV + ((size_t)(i0 + r0) * Sdim + s) * 64 + c) = v0;
            *(float2*)(g_KV + ((size_t)(i0 + r0 + 8) * Sdim + s) * 64 + c) = v1;
        }
        __syncthreads();
    }

#pragma unroll 4
    for (int j = 0; j < 32; ++j) {
        int c = 8 * j + 2 * q;
        atomicAdd(&g_Xsum[(i0 + r) * 256 + c],     xa[2 * j]);
        atomicAdd(&g_Xsum[(i0 + r) * 256 + c + 1], xa[2 * j + 1]);
    }
}

// ================= pass 2a: inline Qbar + attention per column =================
#define KVP 65
__global__ __launch_bounds__(256, 1)
void pass2a_kernel(const float* __restrict__ Wq) {
    extern __shared__ float sm[];
    float* xb  = sm;                 // 256
    float* qb  = sm + 256;           // 256
    float* kvs = sm + 512;           // 256*KVP
    float* sc  = kvs + 256 * KVP;    // 8*256

    const int i = blockIdx.x, tid = threadIdx.x;
    xb[tid] = g_Xsum[i * 256 + tid] * (1.f / (float)Sdim);

    float4 kvr[16];
    {
        const float4* src = (const float4*)(g_KV + (size_t)i * Sdim * 64);
#pragma unroll
        for (int t = 0; t < 16; ++t) kvr[t] = src[tid + t * 256];
    }
    __syncthreads();

    {
        float q0 = 0.f, q1 = 0.f, q2 = 0.f, q3 = 0.f;
#pragma unroll 4
        for (int c = 0; c < 256; c += 4) {
            q0 += xb[c + 0] * Wq[(c + 0) * 256 + tid];
            q1 += xb[c + 1] * Wq[(c + 1) * 256 + tid];
            q2 += xb[c + 2] * Wq[(c + 2) * 256 + tid];
            q3 += xb[c + 3] * Wq[(c + 3) * 256 + tid];
        }
        qb[tid] = (q0 + q1) + (q2 + q3);
    }

#pragma unroll
    for (int t = 0; t < 16; ++t) {
        int idx = tid + t * 256;
        int tt = idx >> 4, j4 = idx & 15;
        float* d = kvs + tt * KVP + j4 * 4;
        d[0] = kvr[t].x; d[1] = kvr[t].y; d[2] = kvr[t].z; d[3] = kvr[t].w;
    }
    __syncthreads();

    const int h = tid >> 5, lt = tid & 31;
    float sv[8];
#pragma unroll
    for (int k = 0; k < 8; ++k) {
        int t = lt + 32 * k;
        float s = 0.f;
#pragma unroll
        for (int d = 0; d < 32; ++d) s += qb[h * 32 + d] * kvs[t * KVP + d];
        sv[k] = s * 0.17677669529663687f;
    }
    float mx = sv[0];
#pragma unroll
    for (int k = 1; k < 8; ++k) mx = fmaxf(mx, sv[k]);
#pragma unroll
    for (int off = 16; off > 0; off >>= 1) mx = fmaxf(mx, __shfl_xor_sync(0xffffffffu, mx, off));
    float sum = 0.f;
#pragma unroll
    for (int k = 0; k < 8; ++k) { sv[k] = __expf(sv[k] - mx); sum += sv[k]; }
#pragma unroll
    for (int off = 16; off > 0; off >>= 1) sum += __shfl_xor_sync(0xffffffffu, sum, off);
    float rinv = 1.f / sum;
#pragma unroll
    for (int k = 0; k < 8; ++k) sc[h * 256 + lt + 32 * k] = sv[k] * rinv;
    __syncthreads();

    const int d = tid & 31;
    float wacc = 0.f;
#pragma unroll 4
    for (int t = 0; t < 256; ++t) wacc += sc[h * 256 + t] * kvs[t * KVP + 32 + d];
    g_Wgt[(size_t)i * 256 + h * 32 + d] = wacc;
}

// ================= pass 2b: mma.sync fp16, full-B-resident + ldmatrix, 512 threads =================
// smem (u32): 0: sbg[256], 256: sbo[256], 512: A[128][132], 17408: B[4 chunks][256][36]
#define SM_AH 512
#define SM_B  17408
#define SM2B_U32 (17408 + 4 * 9216)
#define SM2B_BYTES (SM2B_U32 * 4)

__device__ __forceinline__ void stage_b_full(uint32_t* smu, int g, int tid) {
    const uint4* src = (const uint4*)g_B32hi + (size_t)g * 8192;
#pragma unroll
    for (int t = 0; t < 16; ++t) {
        int u = tid + t * 512;
        int kc = u >> 11, rem = u & 2047;
        int n = rem >> 3, kq = rem & 7;
        *((uint4*)(smu + SM_B + kc * 9216 + n * 36) + kq) = src[u];
    }
}

__device__ __forceinline__ void mma_gemm(const uint32_t* a_base,
                                         const uint32_t* b_base,
                                         float acc[2][8][4]) {
#pragma unroll
    for (int kc = 0; kc < 4; ++kc) {
#pragma unroll
        for (int s = 0; s < 4; ++s) {
            const uint32_t akoff = (uint32_t)(kc * 32 + s * 8) * 4;
            const uint32_t bkoff = (uint32_t)(kc * 9216 + s * 8) * 4;
            uint32_t a[2][4], bb[4][4];
#pragma unroll
            for (int mi = 0; mi < 2; ++mi)
                ldsm_x4(a[mi][0], a[mi][1], a[mi][2], a[mi][3], a_base[mi] + akoff);
#pragma unroll
            for (int np = 0; np < 4; ++np)
                ldsm_x4(bb[np][0], bb[np][1], bb[np][2], bb[np][3], b_base[np] + bkoff);
#pragma unroll
            for (int ni = 0; ni < 8; ++ni) {
                uint32_t b0 = bb[ni >> 1][(ni & 1) * 2];
                uint32_t b1 = bb[ni >> 1][(ni & 1) * 2 + 1];
#pragma unroll
                for (int mi = 0; mi < 2; ++mi) {
                    asm volatile(
                        "mma.sync.aligned.m16n8k16.row.col.f32.f16.f16.f32 "
                        "{%0,%1,%2,%3}, {%4,%5,%6,%7}, {%8,%9}, {%0,%1,%2,%3};"
                        : "+f"(acc[mi][ni][0]), "+f"(acc[mi][ni][1]),
                          "+f"(acc[mi][ni][2]), "+f"(acc[mi][ni][3])
                        : "r"(a[mi][0]), "r"(a[mi][1]), "r"(a[mi][2]), "r"(a[mi][3]),
                          "r"(b0), "r"(b1));
                }
            }
        }
    }
}

__global__ __launch_bounds__(512, 1)
void pass2b_mma_kernel(const float* __restrict__ bg, const float* __restrict__ bo,
                       float* __restrict__ out) {
    extern __shared__ uint32_t smu[];
    float* fsm = (float*)smu;
    const uint32_t smbase = smem_u32(smu);
    const int tid = threadIdx.x;
    const int wid = tid >> 5, lane = tid & 31;
    const int gid = lane >> 2, tig = lane & 3;
    const int m0 = (wid >> 2) * 32, n0 = (wid & 3) * 64;   // 16 warps: 4m x 4n, tile 32x64
    const size_t r0 = (size_t)blockIdx.x * 128;
    const int i0 = (int)(r0 % Idim);

    if (tid < 256) { fsm[tid] = bg[tid]; fsm[256 + tid] = bo[tid]; }

    uint32_t a_base[2], b_base[4];
    {
        int arow = (lane & 7) + 8 * ((lane >> 3) & 1);
        int akl  = 4 * (lane >> 4);
#pragma unroll
        for (int mi = 0; mi < 2; ++mi)
            a_base[mi] = smbase + (uint32_t)(SM_AH + (m0 + mi * 16 + arow) * APITCH + akl) * 4;
        int brow = (lane & 7) + 8 * ((lane >> 4) & 1);
        int bkl  = 4 * ((lane >> 3) & 1);
#pragma unroll
        for (int np = 0; np < 4; ++np)
            b_base[np] = smbase + (uint32_t)(SM_B + (n0 + np * 16 + brow) * BPITCH + bkl) * 4;
    }

    // ---- stage A (pre-LN'd fp16 xn tile) + full Wg ----
    {
        const uint4* xn = (const uint4*)(g_Xn + r0 * 128);
#pragma unroll
        for (int t = 0; t < 8; ++t) {
            int idx4 = tid + t * 512;
            int row = idx4 >> 5, c4 = idx4 & 31;
            *(uint4*)(smu + SM_AH + row * APITCH + c4 * 4) = xn[idx4];
        }
    }
    stage_b_full(smu, 0, tid);
    __syncthreads();

    float acc[2][8][4] = {};

    // ---- GEMM1: xn @ Wg ----
    mma_gemm(a_base, b_base, acc);
    __syncthreads();

    // ---- stage Wo, epilogue 1 ----
    stage_b_full(smu, 1, tid);
#pragma unroll
    for (int mi = 0; mi < 2; ++mi) {
#pragma unroll
        for (int ni = 0; ni < 8; ++ni) {
            int c = n0 + ni * 8 + tig * 2;
#pragma unroll
            for (int half = 0; half < 2; ++half) {
                int r = m0 + mi * 16 + gid + half * 8;
                float2 w = *(const float2*)(g_Wgt + (size_t)(i0 + r) * 256 + c);
                float t0 = acc[mi][ni][half * 2 + 0] + fsm[c];
                float t1 = acc[mi][ni][half * 2 + 1] + fsm[c + 1];
                float v0 = w.x / (1.f + __expf(-t0));
                float v1 = w.y / (1.f + __expf(-t1));
                smu[SM_AH + r * APITCH + (c >> 1)] = pack_f16(v0, v1);
                acc[mi][ni][half * 2 + 0] = 0.f;
                acc[mi][ni][half * 2 + 1] = 0.f;
            }
        }
    }
    __syncthreads();

    // ---- GEMM2: val @ Wo ----
    mma_gemm(a_base, b_base, acc);

    // ---- epilogue 2: out = acc + bo ----
#pragma unroll
    for (int mi = 0; mi < 2; ++mi) {
#pragma unroll
        for (int ni = 0; ni < 8; ++ni) {
            int c = n0 + ni * 8 + tig * 2;
#pragma unroll
            for (int half = 0; half < 2; ++half) {
                int r = m0 + mi * 16 + gid + half * 8;
                float2 v;
                v.x = acc[mi][ni][half * 2 + 0] + fsm[256 + c];
                v.y = acc[mi][ni][half * 2 + 1] + fsm[256 + c + 1];
                *(float2*)(out + (r0 + r) * Cdim + c) = v;
            }
        }
    }
}

// ---------------- launch ----------------
extern "C" void kernel_launch(void* const* d_in, const int* in_sizes, int n_in,
                              void* d_out, int out_size) {
    const float* x     = (const float*)d_in[0];
    const float* gamma = (const float*)d_in[1];
    const float* beta  = (const float*)d_in[2];
    const float* Wq    = (const float*)d_in[3];
    const float* Wk    = (const float*)d_in[4];
    const float* Wv    = (const float*)d_in[5];
    const float* Wg    = (const float*)d_in[6];
    const float* bg    = (const float*)d_in[7];
    const float* Wo    = (const float*)d_in[8];
    const float* bo    = (const float*)d_in[9];
    float* out = (float*)d_out;

    const int SMEM1  = P1_SMEM_U32 * 4;
    const int SMEM2A = (512 + 256 * KVP + 8 * 256) * 4;

    cudaFuncSetAttribute(pass1_kernel,      cudaFuncAttributeMaxDynamicSharedMemorySize, SMEM1);
    cudaFuncSetAttribute(pass2a_kernel,     cudaFuncAttributeMaxDynamicSharedMemorySize, SMEM2A);
    cudaFuncSetAttribute(pass2b_mma_kernel, cudaFuncAttributeMaxDynamicSharedMemorySize, SM2B_BYTES);

    prep_kernel<<<512, 256>>>(Wg, Wo, Wk, Wv);
    pass1_kernel<<<dim3(Idim / 64, Sdim / 8), 256, SMEM1>>>(x, gamma, beta);
    pass2a_kernel<<<Idim, 256, SMEM2A>>>(Wq);
    pass2b_mma_kernel<<<SI / 128, 512, SM2B_BYTES>>>(bg, bo, out);
}